// round 2
// baseline (speedup 1.0000x reference)
#include <cuda_runtime.h>
#include <cstdint>

#define B_    2
#define S_    2048
#define E_    2048
#define H_    16
#define KVH_  4
#define D_    128
#define BS_   (B_*S_)          // 4096
#define SOFTMAX_SCALE 0.08838834764831845f   // 1/sqrt(128)

// ---------------- scratch (static device arrays; no allocation allowed) ----
__device__ float g_Q [BS_ * E_];          // [4096, 2048]  (b*S+s, h*D+d)
__device__ float g_K [BS_ * KVH_ * D_];   // [4096, 512]
__device__ float g_V [BS_ * KVH_ * D_];   // [4096, 512]
__device__ float g_AO[BS_ * E_];          // attention output, pre out-proj

// ===========================================================================
// GEMM: C[M,N] = A[M,K] @ W[N,K]^T    (row-major A, row-major W)
// 128x128 tile, BK=16, 256 threads, 8x8 per-thread micro-tile.
// ===========================================================================
#define GBM 128
#define GBN 128
#define GBK 16

__global__ __launch_bounds__(256) void gemm_xwt(
    const float* __restrict__ A, const float* __restrict__ W,
    float* __restrict__ C, int M, int N, int K)
{
    __shared__ float sA[GBK][GBM + 4];   // stride 132 (mult of 4 -> float4 reads ok)
    __shared__ float sB[GBK][GBN + 4];

    const int tid = threadIdx.x;
    const int tx  = tid & 15;       // n dim
    const int ty  = tid >> 4;       // m dim
    const int bm  = blockIdx.y * GBM;
    const int bn  = blockIdx.x * GBN;

    float acc[8][8];
    #pragma unroll
    for (int i = 0; i < 8; i++)
        #pragma unroll
        for (int j = 0; j < 8; j++) acc[i][j] = 0.0f;

    for (int k0 = 0; k0 < K; k0 += GBK) {
        // load + transpose both tiles (2048 floats each = 512 float4, 2/thread)
        #pragma unroll
        for (int it = 0; it < 2; it++) {
            int f   = tid + it * 256;           // [0,512)
            int row = f >> 2;
            int k4  = (f & 3) * 4;
            float4 av = *(const float4*)&A[(size_t)(bm + row) * K + k0 + k4];
            sA[k4 + 0][row] = av.x; sA[k4 + 1][row] = av.y;
            sA[k4 + 2][row] = av.z; sA[k4 + 3][row] = av.w;
            float4 bv = *(const float4*)&W[(size_t)(bn + row) * K + k0 + k4];
            sB[k4 + 0][row] = bv.x; sB[k4 + 1][row] = bv.y;
            sB[k4 + 2][row] = bv.z; sB[k4 + 3][row] = bv.w;
        }
        __syncthreads();

        #pragma unroll
        for (int k = 0; k < GBK; k++) {
            float a[8], b[8];
            *(float4*)&a[0] = *(const float4*)&sA[k][ty * 8];
            *(float4*)&a[4] = *(const float4*)&sA[k][ty * 8 + 4];
            *(float4*)&b[0] = *(const float4*)&sB[k][tx * 8];
            *(float4*)&b[4] = *(const float4*)&sB[k][tx * 8 + 4];
            #pragma unroll
            for (int i = 0; i < 8; i++)
                #pragma unroll
                for (int j = 0; j < 8; j++)
                    acc[i][j] = fmaf(a[i], b[j], acc[i][j]);
        }
        __syncthreads();
    }

    #pragma unroll
    for (int i = 0; i < 8; i++) {
        float* crow = &C[(size_t)(bm + ty * 8 + i) * N + bn + tx * 8];
        *(float4*)&crow[0] = make_float4(acc[i][0], acc[i][1], acc[i][2], acc[i][3]);
        *(float4*)&crow[4] = make_float4(acc[i][4], acc[i][5], acc[i][6], acc[i][7]);
    }
}

// ===========================================================================
// RoPE (in-place). t is [BS_, nh*D]; pair j in [0,64).
// ===========================================================================
__global__ __launch_bounds__(256) void rope_kernel(
    float* __restrict__ t, const float* __restrict__ fcos,
    const float* __restrict__ fsin, int nh, int total)
{
    int idx = blockIdx.x * blockDim.x + threadIdx.x;
    if (idx >= total) return;
    int j   = idx & 63;
    int h   = (idx >> 6) % nh;
    int row = idx / (64 * nh);
    int s   = row & (S_ - 1);
    float c  = fcos[s * 64 + j];
    float sn = fsin[s * 64 + j];
    float2* p = (float2*)&t[((size_t)row * nh + h) * D_ + 2 * j];
    float2 v = *p;
    *p = make_float2(v.x * c - v.y * sn, v.x * sn + v.y * c);
}

// ===========================================================================
// Flash attention, causal, GQA (head h uses kv head h%4 per jnp.tile).
// BM=BN=64, D=128, 256 threads. Dynamic smem:
//   sQt [128][68]  (k-major, pre-scaled)
//   sKt [128][68]  (k-major K)  -- reused as sV [64][132] (row-major V)
//   sP  [64][65]
// ===========================================================================
#define FBM 64
#define FBN 64
#define FLASH_SMEM ((2 * 128 * 68 + 64 * 65) * 4)

__global__ __launch_bounds__(256) void flash_fwd(
    const float* __restrict__ Q, const float* __restrict__ K,
    const float* __restrict__ V, float* __restrict__ O)
{
    extern __shared__ float sm[];
    float* sQt = sm;                 // 128*68
    float* sKt = sm + 128 * 68;      // 128*68  (aliases sV)
    float* sV  = sKt;                // 64*132 fits in same 8704-float buffer
    float* sP  = sm + 2 * 128 * 68;  // 64*65

    const int tid = threadIdx.x;
    const int tx  = tid & 15;        // col group
    const int ty  = tid >> 4;        // row group
    const int m_blk = blockIdx.x;
    const int bh    = blockIdx.y;
    const int b     = bh >> 4;       // / H_
    const int h     = bh & 15;
    const int kvh   = h & 3;         // h % KVH  (jnp.tile semantics)
    const int m0    = m_blk * FBM;

    // load Q tile, transposed + pre-scaled
    for (int idx = tid; idx < FBM * D_; idx += 256) {
        int m = idx >> 7, d = idx & 127;
        sQt[d * 68 + m] = Q[((size_t)(b * S_ + m0 + m) * H_ + h) * D_ + d] * SOFTMAX_SCALE;
    }

    float mrow[4], lrow[4], o[4][8];
    #pragma unroll
    for (int i = 0; i < 4; i++) {
        mrow[i] = -1e30f; lrow[i] = 0.0f;
        #pragma unroll
        for (int jd = 0; jd < 8; jd++) o[i][jd] = 0.0f;
    }

    for (int nb = 0; nb <= m_blk; nb++) {
        const int n0 = nb * FBN;
        __syncthreads();   // prior PV done reading sV before we overwrite with K
        for (int idx = tid; idx < FBN * D_; idx += 256) {
            int n = idx >> 7, d = idx & 127;
            sKt[d * 68 + n] = K[((size_t)(b * S_ + n0 + n) * KVH_ + kvh) * D_ + d];
        }
        __syncthreads();

        // S = Q K^T  (rows 4*ty+i, cols 4*tx+j)
        float sacc[4][4];
        #pragma unroll
        for (int i = 0; i < 4; i++)
            #pragma unroll
            for (int j = 0; j < 4; j++) sacc[i][j] = 0.0f;

        #pragma unroll 4
        for (int k = 0; k < D_; k++) {
            float av[4], bv[4];
            *(float4*)av = *(const float4*)&sQt[k * 68 + 4 * ty];
            *(float4*)bv = *(const float4*)&sKt[k * 68 + 4 * tx];
            #pragma unroll
            for (int i = 0; i < 4; i++)
                #pragma unroll
                for (int j = 0; j < 4; j++)
                    sacc[i][j] = fmaf(av[i], bv[j], sacc[i][j]);
        }

        // causal mask on diagonal block (m0 == n0 there)
        if (nb == m_blk) {
            #pragma unroll
            for (int i = 0; i < 4; i++)
                #pragma unroll
                for (int j = 0; j < 4; j++)
                    if (4 * tx + j > 4 * ty + i) sacc[i][j] = -1e30f;
        }

        // online softmax per row; row group = 16 lanes sharing ty
        #pragma unroll
        for (int i = 0; i < 4; i++) {
            float mx = fmaxf(fmaxf(sacc[i][0], sacc[i][1]),
                             fmaxf(sacc[i][2], sacc[i][3]));
            #pragma unroll
            for (int off = 8; off; off >>= 1)
                mx = fmaxf(mx, __shfl_xor_sync(0xffffffffu, mx, off, 16));
            float mnew = fmaxf(mrow[i], mx);
            float corr = __expf(mrow[i] - mnew);
            mrow[i] = mnew;
            float rs = 0.0f;
            #pragma unroll
            for (int j = 0; j < 4; j++) {
                float p = __expf(sacc[i][j] - mnew);
                sacc[i][j] = p;
                rs += p;
            }
            #pragma unroll
            for (int off = 8; off; off >>= 1)
                rs += __shfl_xor_sync(0xffffffffu, rs, off, 16);
            lrow[i] = lrow[i] * corr + rs;
            #pragma unroll
            for (int jd = 0; jd < 8; jd++) o[i][jd] *= corr;
            #pragma unroll
            for (int j = 0; j < 4; j++)
                sP[(4 * ty + i) * 65 + 4 * tx + j] = sacc[i][j];
        }
        __syncthreads();   // P visible; everyone done reading sKt

        // load V tile row-major (overwrites sKt buffer)
        for (int i4 = tid; i4 < FBN * D_ / 4; i4 += 256) {
            int n = i4 >> 5, d = (i4 & 31) * 4;
            *(float4*)&sV[n * 132 + d] =
                *(const float4*)&V[((size_t)(b * S_ + n0 + n) * KVH_ + kvh) * D_ + d];
        }
        __syncthreads();

        // O += P V   (thread covers d = 8*tx .. 8*tx+7)
        #pragma unroll 8
        for (int n = 0; n < FBN; n++) {
            float vv[8];
            *(float4*)&vv[0] = *(const float4*)&sV[n * 132 + 8 * tx];
            *(float4*)&vv[4] = *(const float4*)&sV[n * 132 + 8 * tx + 4];
            #pragma unroll
            for (int i = 0; i < 4; i++) {
                float p = sP[(4 * ty + i) * 65 + n];
                #pragma unroll
                for (int jd = 0; jd < 8; jd++)
                    o[i][jd] = fmaf(p, vv[jd], o[i][jd]);
            }
        }
    }

    // epilogue: normalize, write [b, s, h*D+d]
    #pragma unroll
    for (int i = 0; i < 4; i++) {
        float inv = 1.0f / lrow[i];
        int row = b * S_ + m0 + 4 * ty + i;
        float* dst = &O[(size_t)row * E_ + h * D_ + 8 * tx];
        *(float4*)&dst[0] = make_float4(o[i][0] * inv, o[i][1] * inv,
                                        o[i][2] * inv, o[i][3] * inv);
        *(float4*)&dst[4] = make_float4(o[i][4] * inv, o[i][5] * inv,
                                        o[i][6] * inv, o[i][7] * inv);
    }
}

// ===========================================================================
extern "C" void kernel_launch(void* const* d_in, const int* in_sizes, int n_in,
                              void* d_out, int out_size)
{
    const float* x   = (const float*)d_in[0];
    const float* wq  = (const float*)d_in[1];
    const float* wk  = (const float*)d_in[2];
    const float* wv  = (const float*)d_in[3];
    const float* wo  = (const float*)d_in[4];
    const float* fco = (const float*)d_in[5];
    const float* fsi = (const float*)d_in[6];
    float* out = (float*)d_out;

    float *Qb, *Kb, *Vb, *AOb;
    cudaGetSymbolAddress((void**)&Qb,  g_Q);
    cudaGetSymbolAddress((void**)&Kb,  g_K);
    cudaGetSymbolAddress((void**)&Vb,  g_V);
    cudaGetSymbolAddress((void**)&AOb, g_AO);

    cudaFuncSetAttribute(flash_fwd, cudaFuncAttributeMaxDynamicSharedMemorySize,
                         FLASH_SMEM);

    // QKV projections
    gemm_xwt<<<dim3(E_ / GBN, BS_ / GBM), 256>>>(x, wq, Qb, BS_, E_, E_);
    gemm_xwt<<<dim3((KVH_ * D_) / GBN, BS_ / GBM), 256>>>(x, wk, Kb, BS_, KVH_ * D_, E_);
    gemm_xwt<<<dim3((KVH_ * D_) / GBN, BS_ / GBM), 256>>>(x, wv, Vb, BS_, KVH_ * D_, E_);

    // RoPE on Q and K
    rope_kernel<<<(BS_ * H_ * 64 + 255) / 256, 256>>>(Qb, fco, fsi, H_, BS_ * H_ * 64);
    rope_kernel<<<(BS_ * KVH_ * 64 + 255) / 256, 256>>>(Kb, fco, fsi, KVH_, BS_ * KVH_ * 64);

    // causal GQA flash attention
    flash_fwd<<<dim3(S_ / FBM, B_ * H_), 256, FLASH_SMEM>>>(Qb, Kb, Vb, AOb);

    // output projection -> d_out
    gemm_xwt<<<dim3(E_ / GBN, BS_ / GBM), 256>>>(AOb, wo, out, BS_, E_, E_);
}

// round 3
// speedup vs baseline: 1.6263x; 1.6263x over previous
#include <cuda_runtime.h>
#include <cstdint>

#define B_    2
#define S_    2048
#define E_    2048
#define H_    16
#define KVH_  4
#define D_    128
#define BS_   (B_*S_)          // 4096
#define SOFTMAX_SCALE 0.08838834764831845f   // 1/sqrt(128)

// ---------------- scratch (static device arrays; no allocation allowed) ----
__device__ float g_Q [BS_ * E_];          // [4096, 2048]  (b*S+s, h*D+d)
__device__ float g_K [BS_ * KVH_ * D_];   // [4096, 512]
__device__ float g_V [BS_ * KVH_ * D_];   // [4096, 512]
__device__ float g_AO[BS_ * E_];          // attention output, pre out-proj

// ===========================================================================
// tf32 tensor-core GEMM:  C[M,N] = A[M,K] @ W[N,K]^T
// 128x128 tile, BK=32, 256 threads (8 warps, 2x4), warp tile 64x32,
// mma.sync.aligned.m16n8k8.row.col.f32.tf32.tf32.f32
// ===========================================================================
#define GBM 128
#define GBN 128
#define GBK 32
#define SAPITCH 36     // 32 + 4 pad -> conflict-free fragment LDS

__device__ __forceinline__ uint32_t f2tf32(float x) {
    uint32_t r;
    asm("cvt.rna.tf32.f32 %0, %1;" : "=r"(r) : "f"(x));
    return r;
}

__device__ __forceinline__ void mma_tf32(
    float& c0, float& c1, float& c2, float& c3,
    uint32_t a0, uint32_t a1, uint32_t a2, uint32_t a3,
    uint32_t b0, uint32_t b1)
{
    asm volatile(
        "mma.sync.aligned.m16n8k8.row.col.f32.tf32.tf32.f32 "
        "{%0,%1,%2,%3}, {%4,%5,%6,%7}, {%8,%9}, {%0,%1,%2,%3};\n"
        : "+f"(c0), "+f"(c1), "+f"(c2), "+f"(c3)
        : "r"(a0), "r"(a1), "r"(a2), "r"(a3), "r"(b0), "r"(b1));
}

__global__ __launch_bounds__(256) void gemm_xwt_tf32(
    const float* __restrict__ A, const float* __restrict__ W,
    float* __restrict__ C, int M, int N, int K)
{
    __shared__ uint32_t sA[GBM][SAPITCH];   // tf32 bits, [m][k]
    __shared__ uint32_t sB[GBN][SAPITCH];   // tf32 bits, [n][k]

    const int tid   = threadIdx.x;
    const int lane  = tid & 31;
    const int warp  = tid >> 5;
    const int wm    = (warp & 1) * 64;      // warp M offset within block
    const int wn    = (warp >> 1) * 32;     // warp N offset within block
    const int gid   = lane >> 2;            // groupID
    const int tig   = lane & 3;             // thread-in-group
    const int bm    = blockIdx.y * GBM;
    const int bn    = blockIdx.x * GBN;

    float acc[4][4][4];                     // [mi][ni][c0..c3]
    #pragma unroll
    for (int mi = 0; mi < 4; mi++)
        #pragma unroll
        for (int ni = 0; ni < 4; ni++)
            #pragma unroll
            for (int c = 0; c < 4; c++) acc[mi][ni][c] = 0.0f;

    for (int k0 = 0; k0 < K; k0 += GBK) {
        // load tiles: 128 rows x 32 cols each = 1024 float4, 4 per thread
        #pragma unroll
        for (int it = 0; it < 4; it++) {
            int f   = tid + it * 256;       // [0,1024)
            int row = f >> 3;
            int c4  = (f & 7) * 4;
            float4 av = *(const float4*)&A[(size_t)(bm + row) * K + k0 + c4];
            sA[row][c4 + 0] = f2tf32(av.x); sA[row][c4 + 1] = f2tf32(av.y);
            sA[row][c4 + 2] = f2tf32(av.z); sA[row][c4 + 3] = f2tf32(av.w);
            float4 bv = *(const float4*)&W[(size_t)(bn + row) * K + k0 + c4];
            sB[row][c4 + 0] = f2tf32(bv.x); sB[row][c4 + 1] = f2tf32(bv.y);
            sB[row][c4 + 2] = f2tf32(bv.z); sB[row][c4 + 3] = f2tf32(bv.w);
        }
        __syncthreads();

        #pragma unroll
        for (int ks = 0; ks < GBK; ks += 8) {
            uint32_t af[4][4];   // [mi][a0..a3]
            #pragma unroll
            for (int mi = 0; mi < 4; mi++) {
                int rb = wm + mi * 16;
                af[mi][0] = sA[rb + gid    ][ks + tig    ];
                af[mi][1] = sA[rb + gid + 8][ks + tig    ];
                af[mi][2] = sA[rb + gid    ][ks + tig + 4];
                af[mi][3] = sA[rb + gid + 8][ks + tig + 4];
            }
            uint32_t bf[4][2];   // [ni][b0..b1]
            #pragma unroll
            for (int ni = 0; ni < 4; ni++) {
                int nb = wn + ni * 8;
                bf[ni][0] = sB[nb + gid][ks + tig    ];
                bf[ni][1] = sB[nb + gid][ks + tig + 4];
            }
            #pragma unroll
            for (int mi = 0; mi < 4; mi++)
                #pragma unroll
                for (int ni = 0; ni < 4; ni++)
                    mma_tf32(acc[mi][ni][0], acc[mi][ni][1],
                             acc[mi][ni][2], acc[mi][ni][3],
                             af[mi][0], af[mi][1], af[mi][2], af[mi][3],
                             bf[ni][0], bf[ni][1]);
        }
        __syncthreads();
    }

    // epilogue: c0,c1 -> (row gid, cols 2*tig,2*tig+1); c2,c3 -> row gid+8
    #pragma unroll
    for (int mi = 0; mi < 4; mi++) {
        int r0 = bm + wm + mi * 16 + gid;
        #pragma unroll
        for (int ni = 0; ni < 4; ni++) {
            int col = bn + wn + ni * 8 + 2 * tig;
            *(float2*)&C[(size_t)r0 * N + col] =
                make_float2(acc[mi][ni][0], acc[mi][ni][1]);
            *(float2*)&C[(size_t)(r0 + 8) * N + col] =
                make_float2(acc[mi][ni][2], acc[mi][ni][3]);
        }
    }
}

// ===========================================================================
// RoPE (in-place). t is [BS_, nh*D]; pair j in [0,64).
// ===========================================================================
__global__ __launch_bounds__(256) void rope_kernel(
    float* __restrict__ t, const float* __restrict__ fcos,
    const float* __restrict__ fsin, int nh, int total)
{
    int idx = blockIdx.x * blockDim.x + threadIdx.x;
    if (idx >= total) return;
    int j   = idx & 63;
    int h   = (idx >> 6) % nh;
    int row = idx / (64 * nh);
    int s   = row & (S_ - 1);
    float c  = fcos[s * 64 + j];
    float sn = fsin[s * 64 + j];
    float2* p = (float2*)&t[((size_t)row * nh + h) * D_ + 2 * j];
    float2 v = *p;
    *p = make_float2(v.x * c - v.y * sn, v.x * sn + v.y * c);
}

// ===========================================================================
// Flash attention, causal, GQA (head h uses kv head h%4 per jnp.tile).
// BM=BN=64, D=128, 256 threads. (unchanged fp32 path this round)
// ===========================================================================
#define FBM 64
#define FBN 64
#define FLASH_SMEM ((2 * 128 * 68 + 64 * 65) * 4)

__global__ __launch_bounds__(256) void flash_fwd(
    const float* __restrict__ Q, const float* __restrict__ K,
    const float* __restrict__ V, float* __restrict__ O)
{
    extern __shared__ float sm[];
    float* sQt = sm;                 // 128*68
    float* sKt = sm + 128 * 68;      // 128*68  (aliases sV)
    float* sV  = sKt;                // 64*132 fits in same buffer
    float* sP  = sm + 2 * 128 * 68;  // 64*65

    const int tid = threadIdx.x;
    const int tx  = tid & 15;        // col group
    const int ty  = tid >> 4;        // row group
    const int m_blk = blockIdx.x;
    const int bh    = blockIdx.y;
    const int b     = bh >> 4;
    const int h     = bh & 15;
    const int kvh   = h & 3;         // h % KVH  (jnp.tile semantics)
    const int m0    = m_blk * FBM;

    for (int idx = tid; idx < FBM * D_; idx += 256) {
        int m = idx >> 7, d = idx & 127;
        sQt[d * 68 + m] = Q[((size_t)(b * S_ + m0 + m) * H_ + h) * D_ + d] * SOFTMAX_SCALE;
    }

    float mrow[4], lrow[4], o[4][8];
    #pragma unroll
    for (int i = 0; i < 4; i++) {
        mrow[i] = -1e30f; lrow[i] = 0.0f;
        #pragma unroll
        for (int jd = 0; jd < 8; jd++) o[i][jd] = 0.0f;
    }

    for (int nb = 0; nb <= m_blk; nb++) {
        const int n0 = nb * FBN;
        __syncthreads();
        for (int idx = tid; idx < FBN * D_; idx += 256) {
            int n = idx >> 7, d = idx & 127;
            sKt[d * 68 + n] = K[((size_t)(b * S_ + n0 + n) * KVH_ + kvh) * D_ + d];
        }
        __syncthreads();

        float sacc[4][4];
        #pragma unroll
        for (int i = 0; i < 4; i++)
            #pragma unroll
            for (int j = 0; j < 4; j++) sacc[i][j] = 0.0f;

        #pragma unroll 4
        for (int k = 0; k < D_; k++) {
            float av[4], bv[4];
            *(float4*)av = *(const float4*)&sQt[k * 68 + 4 * ty];
            *(float4*)bv = *(const float4*)&sKt[k * 68 + 4 * tx];
            #pragma unroll
            for (int i = 0; i < 4; i++)
                #pragma unroll
                for (int j = 0; j < 4; j++)
                    sacc[i][j] = fmaf(av[i], bv[j], sacc[i][j]);
        }

        if (nb == m_blk) {
            #pragma unroll
            for (int i = 0; i < 4; i++)
                #pragma unroll
                for (int j = 0; j < 4; j++)
                    if (4 * tx + j > 4 * ty + i) sacc[i][j] = -1e30f;
        }

        #pragma unroll
        for (int i = 0; i < 4; i++) {
            float mx = fmaxf(fmaxf(sacc[i][0], sacc[i][1]),
                             fmaxf(sacc[i][2], sacc[i][3]));
            #pragma unroll
            for (int off = 8; off; off >>= 1)
                mx = fmaxf(mx, __shfl_xor_sync(0xffffffffu, mx, off, 16));
            float mnew = fmaxf(mrow[i], mx);
            float corr = __expf(mrow[i] - mnew);
            mrow[i] = mnew;
            float rs = 0.0f;
            #pragma unroll
            for (int j = 0; j < 4; j++) {
                float p = __expf(sacc[i][j] - mnew);
                sacc[i][j] = p;
                rs += p;
            }
            #pragma unroll
            for (int off = 8; off; off >>= 1)
                rs += __shfl_xor_sync(0xffffffffu, rs, off, 16);
            lrow[i] = lrow[i] * corr + rs;
            #pragma unroll
            for (int jd = 0; jd < 8; jd++) o[i][jd] *= corr;
            #pragma unroll
            for (int j = 0; j < 4; j++)
                sP[(4 * ty + i) * 65 + 4 * tx + j] = sacc[i][j];
        }
        __syncthreads();

        for (int i4 = tid; i4 < FBN * D_ / 4; i4 += 256) {
            int n = i4 >> 5, d = (i4 & 31) * 4;
            *(float4*)&sV[n * 132 + d] =
                *(const float4*)&V[((size_t)(b * S_ + n0 + n) * KVH_ + kvh) * D_ + d];
        }
        __syncthreads();

        #pragma unroll 8
        for (int n = 0; n < FBN; n++) {
            float vv[8];
            *(float4*)&vv[0] = *(const float4*)&sV[n * 132 + 8 * tx];
            *(float4*)&vv[4] = *(const float4*)&sV[n * 132 + 8 * tx + 4];
            #pragma unroll
            for (int i = 0; i < 4; i++) {
                float p = sP[(4 * ty + i) * 65 + n];
                #pragma unroll
                for (int jd = 0; jd < 8; jd++)
                    o[i][jd] = fmaf(p, vv[jd], o[i][jd]);
            }
        }
    }

    #pragma unroll
    for (int i = 0; i < 4; i++) {
        float inv = 1.0f / lrow[i];
        int row = b * S_ + m0 + 4 * ty + i;
        float* dst = &O[(size_t)row * E_ + h * D_ + 8 * tx];
        *(float4*)&dst[0] = make_float4(o[i][0] * inv, o[i][1] * inv,
                                        o[i][2] * inv, o[i][3] * inv);
        *(float4*)&dst[4] = make_float4(o[i][4] * inv, o[i][5] * inv,
                                        o[i][6] * inv, o[i][7] * inv);
    }
}

// ===========================================================================
extern "C" void kernel_launch(void* const* d_in, const int* in_sizes, int n_in,
                              void* d_out, int out_size)
{
    const float* x   = (const float*)d_in[0];
    const float* wq  = (const float*)d_in[1];
    const float* wk  = (const float*)d_in[2];
    const float* wv  = (const float*)d_in[3];
    const float* wo  = (const float*)d_in[4];
    const float* fco = (const float*)d_in[5];
    const float* fsi = (const float*)d_in[6];
    float* out = (float*)d_out;

    float *Qb, *Kb, *Vb, *AOb;
    cudaGetSymbolAddress((void**)&Qb,  g_Q);
    cudaGetSymbolAddress((void**)&Kb,  g_K);
    cudaGetSymbolAddress((void**)&Vb,  g_V);
    cudaGetSymbolAddress((void**)&AOb, g_AO);

    cudaFuncSetAttribute(flash_fwd, cudaFuncAttributeMaxDynamicSharedMemorySize,
                         FLASH_SMEM);

    // QKV projections (tf32 tensor cores)
    gemm_xwt_tf32<<<dim3(E_ / GBN, BS_ / GBM), 256>>>(x, wq, Qb, BS_, E_, E_);
    gemm_xwt_tf32<<<dim3((KVH_ * D_) / GBN, BS_ / GBM), 256>>>(x, wk, Kb, BS_, KVH_ * D_, E_);
    gemm_xwt_tf32<<<dim3((KVH_ * D_) / GBN, BS_ / GBM), 256>>>(x, wv, Vb, BS_, KVH_ * D_, E_);

    // RoPE on Q and K
    rope_kernel<<<(BS_ * H_ * 64 + 255) / 256, 256>>>(Qb, fco, fsi, H_, BS_ * H_ * 64);
    rope_kernel<<<(BS_ * KVH_ * 64 + 255) / 256, 256>>>(Kb, fco, fsi, KVH_, BS_ * KVH_ * 64);

    // causal GQA flash attention (fp32)
    flash_fwd<<<dim3(S_ / FBM, B_ * H_), 256, FLASH_SMEM>>>(Qb, Kb, Vb, AOb);

    // output projection -> d_out (tf32 tensor cores)
    gemm_xwt_tf32<<<dim3(E_ / GBN, BS_ / GBM), 256>>>(AOb, wo, out, BS_, E_, E_);
}

// round 4
// speedup vs baseline: 2.4004x; 1.4760x over previous
#include <cuda_runtime.h>
#include <cstdint>

#define B_    2
#define S_    2048
#define E_    2048
#define H_    16
#define KVH_  4
#define D_    128
#define BS_   (B_*S_)          // 4096
#define SOFTMAX_SCALE 0.08838834764831845f   // 1/sqrt(128)

// ---------------- scratch (static device arrays; no allocation allowed) ----
__device__ float g_Q [BS_ * E_];          // [4096, 2048]  (b*S+s, h*D+d)
__device__ float g_K [BS_ * KVH_ * D_];   // [4096, 512]
__device__ float g_V [BS_ * KVH_ * D_];   // [4096, 512]
__device__ float g_AO[BS_ * E_];          // attention output, pre out-proj

// ---------------- tf32 helpers ---------------------------------------------
__device__ __forceinline__ uint32_t f2tf32(float x) {
    uint32_t r;
    asm("cvt.rna.tf32.f32 %0, %1;" : "=r"(r) : "f"(x));
    return r;
}

__device__ __forceinline__ void mma_tf32(
    float& c0, float& c1, float& c2, float& c3,
    uint32_t a0, uint32_t a1, uint32_t a2, uint32_t a3,
    uint32_t b0, uint32_t b1)
{
    asm volatile(
        "mma.sync.aligned.m16n8k8.row.col.f32.tf32.tf32.f32 "
        "{%0,%1,%2,%3}, {%4,%5,%6,%7}, {%8,%9}, {%0,%1,%2,%3};\n"
        : "+f"(c0), "+f"(c1), "+f"(c2), "+f"(c3)
        : "r"(a0), "r"(a1), "r"(a2), "r"(a3), "r"(b0), "r"(b1));
}

// ===========================================================================
// tf32 tensor-core GEMM:  C[M,N] = A[M,K] @ W[N,K]^T   (unchanged from R3)
// ===========================================================================
#define GBM 128
#define GBN 128
#define GBK 32
#define SAPITCH 36

__global__ __launch_bounds__(256) void gemm_xwt_tf32(
    const float* __restrict__ A, const float* __restrict__ W,
    float* __restrict__ C, int M, int N, int K)
{
    __shared__ uint32_t sA[GBM][SAPITCH];
    __shared__ uint32_t sB[GBN][SAPITCH];

    const int tid   = threadIdx.x;
    const int lane  = tid & 31;
    const int warp  = tid >> 5;
    const int wm    = (warp & 1) * 64;
    const int wn    = (warp >> 1) * 32;
    const int gid   = lane >> 2;
    const int tig   = lane & 3;
    const int bm    = blockIdx.y * GBM;
    const int bn    = blockIdx.x * GBN;

    float acc[4][4][4];
    #pragma unroll
    for (int mi = 0; mi < 4; mi++)
        #pragma unroll
        for (int ni = 0; ni < 4; ni++)
            #pragma unroll
            for (int c = 0; c < 4; c++) acc[mi][ni][c] = 0.0f;

    for (int k0 = 0; k0 < K; k0 += GBK) {
        #pragma unroll
        for (int it = 0; it < 4; it++) {
            int f   = tid + it * 256;
            int row = f >> 3;
            int c4  = (f & 7) * 4;
            float4 av = *(const float4*)&A[(size_t)(bm + row) * K + k0 + c4];
            sA[row][c4 + 0] = f2tf32(av.x); sA[row][c4 + 1] = f2tf32(av.y);
            sA[row][c4 + 2] = f2tf32(av.z); sA[row][c4 + 3] = f2tf32(av.w);
            float4 bv = *(const float4*)&W[(size_t)(bn + row) * K + k0 + c4];
            sB[row][c4 + 0] = f2tf32(bv.x); sB[row][c4 + 1] = f2tf32(bv.y);
            sB[row][c4 + 2] = f2tf32(bv.z); sB[row][c4 + 3] = f2tf32(bv.w);
        }
        __syncthreads();

        #pragma unroll
        for (int ks = 0; ks < GBK; ks += 8) {
            uint32_t af[4][4];
            #pragma unroll
            for (int mi = 0; mi < 4; mi++) {
                int rb = wm + mi * 16;
                af[mi][0] = sA[rb + gid    ][ks + tig    ];
                af[mi][1] = sA[rb + gid + 8][ks + tig    ];
                af[mi][2] = sA[rb + gid    ][ks + tig + 4];
                af[mi][3] = sA[rb + gid + 8][ks + tig + 4];
            }
            uint32_t bf[4][2];
            #pragma unroll
            for (int ni = 0; ni < 4; ni++) {
                int nb = wn + ni * 8;
                bf[ni][0] = sB[nb + gid][ks + tig    ];
                bf[ni][1] = sB[nb + gid][ks + tig + 4];
            }
            #pragma unroll
            for (int mi = 0; mi < 4; mi++)
                #pragma unroll
                for (int ni = 0; ni < 4; ni++)
                    mma_tf32(acc[mi][ni][0], acc[mi][ni][1],
                             acc[mi][ni][2], acc[mi][ni][3],
                             af[mi][0], af[mi][1], af[mi][2], af[mi][3],
                             bf[ni][0], bf[ni][1]);
        }
        __syncthreads();
    }

    #pragma unroll
    for (int mi = 0; mi < 4; mi++) {
        int r0 = bm + wm + mi * 16 + gid;
        #pragma unroll
        for (int ni = 0; ni < 4; ni++) {
            int col = bn + wn + ni * 8 + 2 * tig;
            *(float2*)&C[(size_t)r0 * N + col] =
                make_float2(acc[mi][ni][0], acc[mi][ni][1]);
            *(float2*)&C[(size_t)(r0 + 8) * N + col] =
                make_float2(acc[mi][ni][2], acc[mi][ni][3]);
        }
    }
}

// ===========================================================================
// RoPE (in-place).
// ===========================================================================
__global__ __launch_bounds__(256) void rope_kernel(
    float* __restrict__ t, const float* __restrict__ fcos,
    const float* __restrict__ fsin, int nh, int total)
{
    int idx = blockIdx.x * blockDim.x + threadIdx.x;
    if (idx >= total) return;
    int j   = idx & 63;
    int h   = (idx >> 6) % nh;
    int row = idx / (64 * nh);
    int s   = row & (S_ - 1);
    float c  = fcos[s * 64 + j];
    float sn = fsin[s * 64 + j];
    float2* p = (float2*)&t[((size_t)row * nh + h) * D_ + 2 * j];
    float2 v = *p;
    *p = make_float2(v.x * c - v.y * sn, v.x * sn + v.y * c);
}

// ===========================================================================
// Tensor-core flash attention (causal, GQA kvh = h%4).
// 128 threads = 4 warps; warp w owns query rows [16w,16w+16).
// QK^T: tf32x3 (hi*hi + lo*hi + hi*lo)  -> ~fp32 logits
// PV  : single tf32 (P in [0,1], fp32 accum)
// smem: sQ[64][132] fp32 (scaled), sKV[64][136] (K pitch 132 / V pitch 136),
//       sP[4][16][68] tf32-as-float. Total 86016 B -> 2 CTA/SM.
// ===========================================================================
#define FBM 64
#define FBN 64
#define QP  132
#define KP  132
#define VP  136
#define PP  68
#define SQ_OFF  0
#define SKV_OFF (64 * QP)                 // 8448
#define SP_OFF  (SKV_OFF + 64 * VP)       // 17152
#define FLASH_SMEM ((SP_OFF + 4 * 16 * PP) * 4)   // 86016 B

__global__ __launch_bounds__(128) void flash_tc(
    const float* __restrict__ Q, const float* __restrict__ K,
    const float* __restrict__ V, float* __restrict__ O)
{
    extern __shared__ float sm[];
    float* sQ  = sm + SQ_OFF;
    float* sKV = sm + SKV_OFF;
    float* sP  = sm + SP_OFF;

    const int tid  = threadIdx.x;
    const int lane = tid & 31;
    const int warp = tid >> 5;
    const int gid  = lane >> 2;
    const int tig  = lane & 3;
    const int wrow = warp * 16;

    const int m_blk = blockIdx.x;
    const int bh    = blockIdx.y;
    const int b     = bh >> 4;
    const int h     = bh & 15;
    const int kvh   = h & 3;
    const int m0    = m_blk * FBM;

    float* sPw = sP + warp * 16 * PP;

    // ---- load Q tile (scaled) --------------------------------------------
    for (int idx = tid; idx < FBM * 32; idx += 128) {
        int m = idx >> 5, d4 = (idx & 31) * 4;
        float4 v = *(const float4*)&Q[((size_t)(b * S_ + m0 + m) * H_ + h) * D_ + d4];
        sQ[m * QP + d4 + 0] = v.x * SOFTMAX_SCALE;
        sQ[m * QP + d4 + 1] = v.y * SOFTMAX_SCALE;
        sQ[m * QP + d4 + 2] = v.z * SOFTMAX_SCALE;
        sQ[m * QP + d4 + 3] = v.w * SOFTMAX_SCALE;
    }

    float row_m[2] = {-1e30f, -1e30f};
    float row_l[2] = {0.0f, 0.0f};
    float oacc[16][4];
    #pragma unroll
    for (int dt = 0; dt < 16; dt++)
        #pragma unroll
        for (int c = 0; c < 4; c++) oacc[dt][c] = 0.0f;

    for (int nb = 0; nb <= m_blk; nb++) {
        const int n0 = nb * FBN;
        __syncthreads();   // previous PV finished reading sKV
        for (int idx = tid; idx < FBN * 32; idx += 128) {
            int n = idx >> 5, d4 = (idx & 31) * 4;
            *(float4*)&sKV[n * KP + d4] =
                *(const float4*)&K[((size_t)(b * S_ + n0 + n) * KVH_ + kvh) * D_ + d4];
        }
        __syncthreads();

        // ---- S = Q K^T  (tf32x3) -----------------------------------------
        float sc[8][4];
        #pragma unroll
        for (int ni = 0; ni < 8; ni++)
            #pragma unroll
            for (int c = 0; c < 4; c++) sc[ni][c] = 0.0f;

        #pragma unroll 2
        for (int ks = 0; ks < D_; ks += 8) {
            float a0 = sQ[(wrow + gid    ) * QP + ks + tig    ];
            float a1 = sQ[(wrow + gid + 8) * QP + ks + tig    ];
            float a2 = sQ[(wrow + gid    ) * QP + ks + tig + 4];
            float a3 = sQ[(wrow + gid + 8) * QP + ks + tig + 4];
            uint32_t ah[4] = {f2tf32(a0), f2tf32(a1), f2tf32(a2), f2tf32(a3)};
            uint32_t al[4] = {f2tf32(a0 - __uint_as_float(ah[0])),
                              f2tf32(a1 - __uint_as_float(ah[1])),
                              f2tf32(a2 - __uint_as_float(ah[2])),
                              f2tf32(a3 - __uint_as_float(ah[3]))};
            #pragma unroll
            for (int ni = 0; ni < 8; ni++) {
                float b0 = sKV[(8 * ni + gid) * KP + ks + tig    ];
                float b1 = sKV[(8 * ni + gid) * KP + ks + tig + 4];
                uint32_t bh0 = f2tf32(b0), bh1 = f2tf32(b1);
                uint32_t bl0 = f2tf32(b0 - __uint_as_float(bh0));
                uint32_t bl1 = f2tf32(b1 - __uint_as_float(bh1));
                mma_tf32(sc[ni][0], sc[ni][1], sc[ni][2], sc[ni][3],
                         ah[0], ah[1], ah[2], ah[3], bh0, bh1);
                mma_tf32(sc[ni][0], sc[ni][1], sc[ni][2], sc[ni][3],
                         al[0], al[1], al[2], al[3], bh0, bh1);
                mma_tf32(sc[ni][0], sc[ni][1], sc[ni][2], sc[ni][3],
                         ah[0], ah[1], ah[2], ah[3], bl0, bl1);
            }
        }

        // ---- causal mask on diagonal tile --------------------------------
        if (nb == m_blk) {
            int r0 = wrow + gid, r1 = r0 + 8;
            #pragma unroll
            for (int ni = 0; ni < 8; ni++) {
                int c0 = 8 * ni + 2 * tig, c1 = c0 + 1;
                if (c0 > r0) sc[ni][0] = -1e30f;
                if (c1 > r0) sc[ni][1] = -1e30f;
                if (c0 > r1) sc[ni][2] = -1e30f;
                if (c1 > r1) sc[ni][3] = -1e30f;
            }
        }

        // ---- online softmax (rows r0 = wrow+gid, r1 = +8) ----------------
        float mx0 = -1e30f, mx1 = -1e30f;
        #pragma unroll
        for (int ni = 0; ni < 8; ni++) {
            mx0 = fmaxf(mx0, fmaxf(sc[ni][0], sc[ni][1]));
            mx1 = fmaxf(mx1, fmaxf(sc[ni][2], sc[ni][3]));
        }
        #pragma unroll
        for (int off = 1; off <= 2; off <<= 1) {
            mx0 = fmaxf(mx0, __shfl_xor_sync(0xffffffffu, mx0, off));
            mx1 = fmaxf(mx1, __shfl_xor_sync(0xffffffffu, mx1, off));
        }
        float mn0 = fmaxf(row_m[0], mx0);
        float mn1 = fmaxf(row_m[1], mx1);
        float cr0 = __expf(row_m[0] - mn0);
        float cr1 = __expf(row_m[1] - mn1);
        row_m[0] = mn0; row_m[1] = mn1;

        float s0 = 0.0f, s1 = 0.0f;
        #pragma unroll
        for (int ni = 0; ni < 8; ni++) {
            float p0 = __expf(sc[ni][0] - mn0);
            float p1 = __expf(sc[ni][1] - mn0);
            float p2 = __expf(sc[ni][2] - mn1);
            float p3 = __expf(sc[ni][3] - mn1);
            s0 += p0 + p1; s1 += p2 + p3;
            int cc = 8 * ni + 2 * tig;
            sPw[ gid      * PP + cc    ] = __uint_as_float(f2tf32(p0));
            sPw[ gid      * PP + cc + 1] = __uint_as_float(f2tf32(p1));
            sPw[(gid + 8) * PP + cc    ] = __uint_as_float(f2tf32(p2));
            sPw[(gid + 8) * PP + cc + 1] = __uint_as_float(f2tf32(p3));
        }
        #pragma unroll
        for (int off = 1; off <= 2; off <<= 1) {
            s0 += __shfl_xor_sync(0xffffffffu, s0, off);
            s1 += __shfl_xor_sync(0xffffffffu, s1, off);
        }
        row_l[0] = row_l[0] * cr0 + s0;
        row_l[1] = row_l[1] * cr1 + s1;
        #pragma unroll
        for (int dt = 0; dt < 16; dt++) {
            oacc[dt][0] *= cr0; oacc[dt][1] *= cr0;
            oacc[dt][2] *= cr1; oacc[dt][3] *= cr1;
        }

        __syncthreads();   // all warps done reading sKV(K); P written
        for (int idx = tid; idx < FBN * 32; idx += 128) {
            int n = idx >> 5, d4 = (idx & 31) * 4;
            *(float4*)&sKV[n * VP + d4] =
                *(const float4*)&V[((size_t)(b * S_ + n0 + n) * KVH_ + kvh) * D_ + d4];
        }
        __syncthreads();

        // ---- O += P V  (single tf32) -------------------------------------
        #pragma unroll 2
        for (int kb = 0; kb < FBN; kb += 8) {
            uint32_t pa0 = __float_as_uint(sPw[ gid      * PP + kb + tig    ]);
            uint32_t pa1 = __float_as_uint(sPw[(gid + 8) * PP + kb + tig    ]);
            uint32_t pa2 = __float_as_uint(sPw[ gid      * PP + kb + tig + 4]);
            uint32_t pa3 = __float_as_uint(sPw[(gid + 8) * PP + kb + tig + 4]);
            #pragma unroll
            for (int dt = 0; dt < 16; dt++) {
                uint32_t vb0 = f2tf32(sKV[(kb + tig    ) * VP + 8 * dt + gid]);
                uint32_t vb1 = f2tf32(sKV[(kb + tig + 4) * VP + 8 * dt + gid]);
                mma_tf32(oacc[dt][0], oacc[dt][1], oacc[dt][2], oacc[dt][3],
                         pa0, pa1, pa2, pa3, vb0, vb1);
            }
        }
    }

    // ---- epilogue ---------------------------------------------------------
    float inv0 = 1.0f / row_l[0];
    float inv1 = 1.0f / row_l[1];
    int r0 = b * S_ + m0 + wrow + gid;
    #pragma unroll
    for (int dt = 0; dt < 16; dt++) {
        int col = h * D_ + 8 * dt + 2 * tig;
        *(float2*)&O[(size_t)r0 * E_ + col] =
            make_float2(oacc[dt][0] * inv0, oacc[dt][1] * inv0);
        *(float2*)&O[(size_t)(r0 + 8) * E_ + col] =
            make_float2(oacc[dt][2] * inv1, oacc[dt][3] * inv1);
    }
}

// ===========================================================================
extern "C" void kernel_launch(void* const* d_in, const int* in_sizes, int n_in,
                              void* d_out, int out_size)
{
    const float* x   = (const float*)d_in[0];
    const float* wq  = (const float*)d_in[1];
    const float* wk  = (const float*)d_in[2];
    const float* wv  = (const float*)d_in[3];
    const float* wo  = (const float*)d_in[4];
    const float* fco = (const float*)d_in[5];
    const float* fsi = (const float*)d_in[6];
    float* out = (float*)d_out;

    float *Qb, *Kb, *Vb, *AOb;
    cudaGetSymbolAddress((void**)&Qb,  g_Q);
    cudaGetSymbolAddress((void**)&Kb,  g_K);
    cudaGetSymbolAddress((void**)&Vb,  g_V);
    cudaGetSymbolAddress((void**)&AOb, g_AO);

    cudaFuncSetAttribute(flash_tc, cudaFuncAttributeMaxDynamicSharedMemorySize,
                         FLASH_SMEM);

    // QKV projections (tf32 tensor cores)
    gemm_xwt_tf32<<<dim3(E_ / GBN, BS_ / GBM), 256>>>(x, wq, Qb, BS_, E_, E_);
    gemm_xwt_tf32<<<dim3((KVH_ * D_) / GBN, BS_ / GBM), 256>>>(x, wk, Kb, BS_, KVH_ * D_, E_);
    gemm_xwt_tf32<<<dim3((KVH_ * D_) / GBN, BS_ / GBM), 256>>>(x, wv, Vb, BS_, KVH_ * D_, E_);

    // RoPE on Q and K
    rope_kernel<<<(BS_ * H_ * 64 + 255) / 256, 256>>>(Qb, fco, fsi, H_, BS_ * H_ * 64);
    rope_kernel<<<(BS_ * KVH_ * 64 + 255) / 256, 256>>>(Kb, fco, fsi, KVH_, BS_ * KVH_ * 64);

    // tensor-core causal GQA flash attention
    flash_tc<<<dim3(S_ / FBM, B_ * H_), 128, FLASH_SMEM>>>(Qb, Kb, Vb, AOb);

    // output projection -> d_out (tf32 tensor cores)
    gemm_xwt_tf32<<<dim3(E_ / GBN, BS_ / GBM), 256>>>(AOb, wo, out, BS_, E_, E_);
}